// round 1
// baseline (speedup 1.0000x reference)
#include <cuda_runtime.h>

#define MAXN 40000
#define MAXE 640000
#define HF 128
#define NH 8
#define NF 16

// ---------------- scratch (device globals: no runtime allocation) ----------------
__device__ float g_xp[MAXN * HF];     // transformed features [N,128]
__device__ float g_as[MAXN * NH];     // per-node src attention logits [N,8]
__device__ float g_ad[MAXN * NH];     // per-node dst attention logits [N,8]
__device__ float g_h [MAXN * HF];     // pre-BN output [N,128]
__device__ int   g_deg[MAXN];
__device__ int   g_cnt[MAXN];
__device__ int   g_off[MAXN + 1];
__device__ int   g_srcs[MAXE];        // CSR (by dst) source indices
__device__ float g_cs[HF];            // column sums
__device__ float g_cq[HF];            // column sums of squares

// ---------------- f32x2 packed helpers ----------------
__device__ __forceinline__ unsigned long long pk2(float a, float b) {
    unsigned long long r;
    asm("mov.b64 %0, {%1,%2};" : "=l"(r) : "f"(a), "f"(b));
    return r;
}
__device__ __forceinline__ void upk2(unsigned long long v, float& a, float& b) {
    asm("mov.b64 {%0,%1}, %2;" : "=f"(a), "=f"(b) : "l"(v));
}
__device__ __forceinline__ unsigned long long fma2(unsigned long long a,
                                                   unsigned long long b,
                                                   unsigned long long c) {
    unsigned long long d;
    asm("fma.rn.f32x2 %0, %1, %2, %3;" : "=l"(d) : "l"(a), "l"(b), "l"(c));
    return d;
}

__device__ __forceinline__ float sel8(const float v[8], int idx) {
    float r = v[0];
#pragma unroll
    for (int h = 1; h < 8; h++) r = (idx == h) ? v[h] : r;
    return r;
}

// ---------------- K0: zero scratch ----------------
__global__ void zero_kernel(int n) {
    int i = blockIdx.x * blockDim.x + threadIdx.x;
    if (i < n) { g_deg[i] = 0; g_cnt[i] = 0; }
    if (i < HF) { g_cs[i] = 0.f; g_cq[i] = 0.f; }
}

// ---------------- K1: GEMM xp = x @ W   (M=n, N=128, K=128) ----------------
// 64-row x 128-col tile per block, 256 threads, thread computes 8x4 micro-tile,
// packed f32x2 FMA for full-rate fp32.
__global__ __launch_bounds__(256) void gemm_kernel(const float* __restrict__ X,
                                                   const float* __restrict__ W,
                                                   int n) {
    __shared__ float xs[64][36];     // 36 pad: 16B-aligned rows, conflict-free bcast
    __shared__ float ws[32][128];

    int t  = threadIdx.x;
    int tx = t & 31;                 // column group: cols 4*tx..4*tx+3
    int ty = t >> 5;                 // row group:    rows ty*8..ty*8+7
    int row0 = blockIdx.x * 64;

    unsigned long long acc[8][2];
#pragma unroll
    for (int i = 0; i < 8; i++) { acc[i][0] = 0ull; acc[i][1] = 0ull; }

    for (int kk = 0; kk < 128; kk += 32) {
        // load x tile: 64x32 floats = 512 float4, 2 per thread
#pragma unroll
        for (int rep = 0; rep < 2; rep++) {
            int id = t + rep * 256;
            int r  = id >> 3;
            int c4 = id & 7;
            int row = row0 + r; if (row >= n) row = n - 1;
            float4 v = *(const float4*)(X + (long long)row * 128 + kk + c4 * 4);
            *(float4*)&xs[r][c4 * 4] = v;
        }
        // load W tile: 32x128 floats = 1024 float4, 4 per thread
#pragma unroll
        for (int rep = 0; rep < 4; rep++) {
            int id = t + rep * 256;
            int r  = id >> 5;
            int c4 = id & 31;
            float4 v = *(const float4*)(W + (kk + r) * 128 + c4 * 4);
            *(float4*)&ws[r][c4 * 4] = v;
        }
        __syncthreads();
#pragma unroll
        for (int k = 0; k < 32; k++) {
            float4 w = *(const float4*)&ws[k][tx * 4];
            unsigned long long w01 = pk2(w.x, w.y);
            unsigned long long w23 = pk2(w.z, w.w);
#pragma unroll
            for (int i = 0; i < 8; i++) {
                float xv = xs[ty * 8 + i][k];
                unsigned long long xd = pk2(xv, xv);
                acc[i][0] = fma2(w01, xd, acc[i][0]);
                acc[i][1] = fma2(w23, xd, acc[i][1]);
            }
        }
        __syncthreads();
    }
#pragma unroll
    for (int i = 0; i < 8; i++) {
        int row = row0 + ty * 8 + i;
        if (row < n) {
            float4 o;
            upk2(acc[i][0], o.x, o.y);
            upk2(acc[i][1], o.z, o.w);
            *(float4*)(g_xp + (long long)row * 128 + tx * 4) = o;
        }
    }
}

// ---------------- K2: per-node attention projections a_s, a_d ----------------
__global__ void attnproj_kernel(const float* __restrict__ att_s,
                                const float* __restrict__ att_d, int n) {
    int i = blockIdx.x * blockDim.x + threadIdx.x;   // one per (node, head)
    if (i >= n * NH) return;
    int h = i & 7;
    const float4* p  = (const float4*)(g_xp + (long long)i * NF);
    const float4* sa = (const float4*)(att_s + h * NF);
    const float4* da = (const float4*)(att_d + h * NF);
    float s = 0.f, d = 0.f;
#pragma unroll
    for (int q = 0; q < 4; q++) {
        float4 xv = p[q], sv = sa[q], dv = da[q];
        s += xv.x * sv.x + xv.y * sv.y + xv.z * sv.z + xv.w * sv.w;
        d += xv.x * dv.x + xv.y * dv.y + xv.z * dv.z + xv.w * dv.w;
    }
    g_as[i] = s;
    g_ad[i] = d;
}

// ---------------- K3a: degree histogram over dst ----------------
__global__ void hist_kernel(const int* __restrict__ ei, int e) {
    int i = blockIdx.x * blockDim.x + threadIdx.x;
    if (i < e) atomicAdd(&g_deg[ei[e + i]], 1);
}

// ---------------- K3b: exclusive scan -> offsets (single block) ----------------
__global__ __launch_bounds__(1024) void scan_kernel(int n) {
    const int T = 1024;
    int t = threadIdx.x;
    int chunk = (n + T - 1) / T;
    int start = t * chunk;
    int end   = min(start + chunk, n);
    int sum = 0;
    for (int i = start; i < end; i++) sum += g_deg[i];

    __shared__ int wsum[32];
    int lane = t & 31, wid = t >> 5;
    int v = sum;
#pragma unroll
    for (int o = 1; o < 32; o <<= 1) {
        int u = __shfl_up_sync(0xffffffffu, v, o);
        if (lane >= o) v += u;
    }
    if (lane == 31) wsum[wid] = v;
    __syncthreads();
    if (wid == 0) {
        int w = wsum[lane];
#pragma unroll
        for (int o = 1; o < 32; o <<= 1) {
            int u = __shfl_up_sync(0xffffffffu, w, o);
            if (lane >= o) w += u;
        }
        wsum[lane] = w;
    }
    __syncthreads();
    int excl = v - sum + (wid > 0 ? wsum[wid - 1] : 0);
    int run = excl;
    for (int i = start; i < end; i++) {
        g_off[i] = run;
        run += g_deg[i];
    }
    if (start < n && end == n) g_off[n] = run;
}

// ---------------- K3c: scatter edges into CSR-by-dst ----------------
__global__ void scatter_kernel(const int* __restrict__ ei, int e) {
    int i = blockIdx.x * blockDim.x + threadIdx.x;
    if (i >= e) return;
    int s = ei[i];
    int d = ei[e + i];
    int pos = g_off[d] + atomicAdd(&g_cnt[d], 1);
    g_srcs[pos] = s;
}

// ---------------- K4: per-node softmax-aggregate (one warp per node) ----------------
__global__ __launch_bounds__(256) void aggregate_kernel(const float* __restrict__ bias, int n) {
    int warp = (blockIdx.x * blockDim.x + threadIdx.x) >> 5;
    int lane = threadIdx.x & 31;
    if (warp >= n) return;
    int node = warp;
    int beg = g_off[node], end2 = g_off[node + 1];
    int deg = end2 - beg;

    float adv[8], asv[8];
#pragma unroll
    for (int h = 0; h < 8; h++) {
        adv[h] = g_ad[node * 8 + h];
        asv[h] = g_as[node * 8 + h];
    }
    // init max with self-loop logit (also guards isolated nodes)
    float m[8];
#pragma unroll
    for (int h = 0; h < 8; h++) {
        float v = asv[h] + adv[h];
        m[h] = fmaxf(v, 0.2f * v);
    }
    // pass A: per-head max over neighbors (lane-strided)
    for (int i = beg + lane; i < end2; i += 32) {
        int s = g_srcs[i];
        const float4* ap = (const float4*)(g_as + (long long)s * 8);
        float4 a0 = ap[0], a1 = ap[1];
        float av[8] = {a0.x, a0.y, a0.z, a0.w, a1.x, a1.y, a1.z, a1.w};
#pragma unroll
        for (int h = 0; h < 8; h++) {
            float v = av[h] + adv[h];
            float e = fmaxf(v, 0.2f * v);
            m[h] = fmaxf(m[h], e);
        }
    }
#pragma unroll
    for (int h = 0; h < 8; h++) {
#pragma unroll
        for (int o = 16; o >= 1; o >>= 1)
            m[h] = fmaxf(m[h], __shfl_xor_sync(0xffffffffu, m[h], o));
    }

    // pass B roles: group jB (4 edges/iter) x head hB
    int hB = lane & 7;
    int jB = lane >> 3;
    float mB  = sel8(m, hB);
    float adB = sel8(adv, hB);
    float asB = sel8(asv, hB);
    float vself = asB + adB;
    float eself = fmaxf(vself, 0.2f * vself);
    float pself = __expf(eself - mB);
    float ssum = (jB == 0) ? pself : 0.f;

    float4 acc = make_float4(0.f, 0.f, 0.f, 0.f);
    for (int c = 0; c < deg; c += 4) {
        int  eoff  = c + jB;
        bool valid = eoff < deg;
        int  s = valid ? g_srcs[beg + eoff] : 0;
        float asx = g_as[s * 8 + hB];
        float v = asx + adB;
        float e = fmaxf(v, 0.2f * v);
        float p = valid ? __expf(e - mB) : 0.f;
        ssum += p;

        int s0 = __shfl_sync(0xffffffffu, s, 0);
        int s1 = __shfl_sync(0xffffffffu, s, 8);
        int s2 = __shfl_sync(0xffffffffu, s, 16);
        int s3 = __shfl_sync(0xffffffffu, s, 24);
        float4 x0 = *(const float4*)(g_xp + (long long)s0 * 128 + lane * 4);
        float4 x1 = *(const float4*)(g_xp + (long long)s1 * 128 + lane * 4);
        float4 x2 = *(const float4*)(g_xp + (long long)s2 * 128 + lane * 4);
        float4 x3 = *(const float4*)(g_xp + (long long)s3 * 128 + lane * 4);
        int srcl = lane >> 2;   // lane holding head (lane>>2) in each group
        float p0 = __shfl_sync(0xffffffffu, p, 0 + srcl);
        float p1 = __shfl_sync(0xffffffffu, p, 8 + srcl);
        float p2 = __shfl_sync(0xffffffffu, p, 16 + srcl);
        float p3 = __shfl_sync(0xffffffffu, p, 24 + srcl);
        acc.x += p0 * x0.x + p1 * x1.x + p2 * x2.x + p3 * x3.x;
        acc.y += p0 * x0.y + p1 * x1.y + p2 * x2.y + p3 * x3.y;
        acc.z += p0 * x0.z + p1 * x1.z + p2 * x2.z + p3 * x3.z;
        acc.w += p0 * x0.w + p1 * x1.w + p2 * x2.w + p3 * x3.w;
    }
    // total softmax denominator per head (sum over the 4 groups)
    ssum += __shfl_xor_sync(0xffffffffu, ssum, 8);
    ssum += __shfl_xor_sync(0xffffffffu, ssum, 16);
    float sacc     = __shfl_sync(0xffffffffu, ssum,  lane >> 2);
    float pselfacc = __shfl_sync(0xffffffffu, pself, lane >> 2);
    float inv = 1.0f / (sacc + 1e-16f);

    float4 xn = *(const float4*)(g_xp + (long long)node * 128 + lane * 4);
    float4 b4 = *(const float4*)(bias + lane * 4);
    float4 hv;
    hv.x = (acc.x + pselfacc * xn.x) * inv + b4.x;
    hv.y = (acc.y + pselfacc * xn.y) * inv + b4.y;
    hv.z = (acc.z + pselfacc * xn.z) * inv + b4.z;
    hv.w = (acc.w + pselfacc * xn.w) * inv + b4.w;
    *(float4*)(g_h + (long long)node * 128 + lane * 4) = hv;
}

// ---------------- K5: BN column statistics ----------------
__global__ __launch_bounds__(128) void colstats_kernel(int n) {
    int c = threadIdx.x;   // 128 threads = 128 columns
    float s = 0.f, q = 0.f;
    for (int r = blockIdx.x; r < n; r += gridDim.x) {
        float v = g_h[(long long)r * 128 + c];
        s += v;
        q += v * v;
    }
    atomicAdd(&g_cs[c], s);
    atomicAdd(&g_cq[c], q);
}

// ---------------- K6: BN + ReLU + residual ----------------
__global__ void finalize_kernel(const float* __restrict__ x,
                                const float* __restrict__ gamma,
                                const float* __restrict__ beta,
                                float* __restrict__ out, int n) {
    long long i = (long long)blockIdx.x * blockDim.x + threadIdx.x;
    if (i >= (long long)n * 128) return;
    int c = (int)(i & 127);
    float invn = 1.0f / (float)n;
    float mean = g_cs[c] * invn;
    float var  = g_cq[c] * invn - mean * mean;
    float hv = g_h[i];
    float y = (hv - mean) * rsqrtf(var + 1e-5f) * gamma[c] + beta[c];
    y = fmaxf(y, 0.f) + x[i];
    out[i] = y;
}

// ---------------- launch ----------------
extern "C" void kernel_launch(void* const* d_in, const int* in_sizes, int n_in,
                              void* d_out, int out_size) {
    const float* x       = (const float*)d_in[0];
    const int*   ei      = (const int*)d_in[1];
    const float* W       = (const float*)d_in[2];
    const float* att_src = (const float*)d_in[3];
    const float* att_dst = (const float*)d_in[4];
    const float* bias    = (const float*)d_in[5];
    const float* gamma   = (const float*)d_in[6];
    const float* beta    = (const float*)d_in[7];
    float* out = (float*)d_out;

    int n = in_sizes[0] / HF;       // 40000
    int e = in_sizes[1] / 2;        // 640000

    zero_kernel<<<(n + 255) / 256, 256>>>(n);
    gemm_kernel<<<(n + 63) / 64, 256>>>(x, W, n);
    attnproj_kernel<<<(n * NH + 255) / 256, 256>>>(att_src, att_dst, n);
    hist_kernel<<<(e + 255) / 256, 256>>>(ei, e);
    scan_kernel<<<1, 1024>>>(n);
    scatter_kernel<<<(e + 255) / 256, 256>>>(ei, e);
    aggregate_kernel<<<(n * 32 + 255) / 256, 256>>>(bias, n);
    colstats_kernel<<<256, 128>>>(n);
    finalize_kernel<<<(int)(((long long)n * 128 + 255) / 256), 256>>>(x, gamma, beta, out, n);
}